// round 1
// baseline (speedup 1.0000x reference)
#include <cuda_runtime.h>
#include <math.h>
#include <stdint.h>

// GAT layer: B=8, N=1024, IN=256, OUT=256 (H=4 heads x D=64)
// out[b,n,h*64+d] = sum_j softmax_j(leaky(src[b,h,n]+dst[b,h,j]) masked by adj) * Wh[b,j,h,d]

#define B_ 8
#define N_ 1024
#define K_ 256
#define O_ 256
#define H_ 4
#define D_ 64

__device__ float g_Wh[B_ * N_ * O_];      // [b*N+n][o]  (o = h*64+d), 32 MB
__device__ float g_src[B_ * H_ * N_];
__device__ float g_dst[B_ * H_ * N_];
__device__ int   g_maskKind;              // 0=uint8, 1=int32, 2=float32

// ---------------------------------------------------------------------------
// Kernel A: classify the bool-mask encoding. adj[0][0][0] is guaranteed true
// (self-loop), so the data always contains ones. Word analysis over the first
// 64K words (safe for all encodings: min size = 8388608 bytes = 2M words):
//   any word == 0x3F800000  -> float32 (bytes of {0,1} can never form this)
//   else any word > 1       -> uint8   (packed 0/1 bytes, density 10% -> certain)
//   else                    -> int32   (every word is 0 or 1)
// ---------------------------------------------------------------------------
__global__ void detect_mask_kind(const unsigned int* __restrict__ w) {
    __shared__ int sFloat, sBig;
    if (threadIdx.x == 0) { sFloat = 0; sBig = 0; }
    __syncthreads();
    for (int i = threadIdx.x; i < 65536; i += blockDim.x) {
        unsigned int v = w[i];
        if (v == 0x3F800000u) atomicOr(&sFloat, 1);
        else if (v > 1u) atomicOr(&sBig, 1);
    }
    __syncthreads();
    if (threadIdx.x == 0)
        g_maskKind = sFloat ? 2 : (sBig ? 0 : 1);
}

// ---------------------------------------------------------------------------
// Kernel B: Wh = h @ W^T.  M=8192, K=256, O=256. 64x64 tile, 256 threads,
// 4x4 micro-tile per thread, K-tiles of 16.
// ---------------------------------------------------------------------------
__global__ void gemm_kernel(const float* __restrict__ A, const float* __restrict__ Wt) {
    __shared__ float As[16][64];
    __shared__ float Bs[16][64];

    int tid = threadIdx.x;
    int tx = tid & 15;        // 0..15 -> output cols
    int ty = tid >> 4;        // 0..15 -> output rows
    int m0 = blockIdx.x * 64;
    int o0 = blockIdx.y * 64;

    int lr = tid >> 2;        // 0..63  row within tile to load
    int lk = (tid & 3) * 4;   // 0,4,8,12

    float acc[4][4] = {};

    for (int k0 = 0; k0 < K_; k0 += 16) {
        float4 av = *reinterpret_cast<const float4*>(A  + (size_t)(m0 + lr) * K_ + k0 + lk);
        float4 bv = *reinterpret_cast<const float4*>(Wt + (size_t)(o0 + lr) * K_ + k0 + lk);
        As[lk + 0][lr] = av.x; As[lk + 1][lr] = av.y;
        As[lk + 2][lr] = av.z; As[lk + 3][lr] = av.w;
        Bs[lk + 0][lr] = bv.x; Bs[lk + 1][lr] = bv.y;
        Bs[lk + 2][lr] = bv.z; Bs[lk + 3][lr] = bv.w;
        __syncthreads();

        #pragma unroll
        for (int k = 0; k < 16; ++k) {
            float a[4], b[4];
            #pragma unroll
            for (int i = 0; i < 4; ++i) a[i] = As[k][ty * 4 + i];
            #pragma unroll
            for (int j = 0; j < 4; ++j) b[j] = Bs[k][tx * 4 + j];
            #pragma unroll
            for (int i = 0; i < 4; ++i)
                #pragma unroll
                for (int j = 0; j < 4; ++j)
                    acc[i][j] = fmaf(a[i], b[j], acc[i][j]);
        }
        __syncthreads();
    }

    #pragma unroll
    for (int i = 0; i < 4; ++i)
        #pragma unroll
        for (int j = 0; j < 4; ++j)
            g_Wh[(size_t)(m0 + ty * 4 + i) * O_ + o0 + tx * 4 + j] = acc[i][j];
}

// ---------------------------------------------------------------------------
// Kernel C: src[b,h,n] = Wh[b,n,h,:].a[h,:D], dst uses a[h,D:]. Warp per row.
// ---------------------------------------------------------------------------
__global__ void srcdst_kernel(const float* __restrict__ a) {
    int warp = (blockIdx.x * blockDim.x + threadIdx.x) >> 5;
    int lane = threadIdx.x & 31;
    if (warp >= B_ * H_ * N_) return;
    int n = warp % N_;
    int h = (warp / N_) % H_;
    int b = warp / (N_ * H_);

    const float* wh = g_Wh + (size_t)(b * N_ + n) * O_ + h * D_;
    const float* ah = a + h * (2 * D_);
    float s = 0.f, t = 0.f;
    #pragma unroll
    for (int d = lane; d < D_; d += 32) {
        float w = wh[d];
        s = fmaf(w, __ldg(ah + d), s);
        t = fmaf(w, __ldg(ah + D_ + d), t);
    }
    #pragma unroll
    for (int off = 16; off; off >>= 1) {
        s += __shfl_down_sync(0xFFFFFFFFu, s, off);
        t += __shfl_down_sync(0xFFFFFFFFu, t, off);
    }
    if (lane == 0) { g_src[warp] = s; g_dst[warp] = t; }
}

// ---------------------------------------------------------------------------
// Kernel D: one block per (b,h,i) row. 256 threads.
//   pass1: e_j = leaky(src_i + dst_j) for valid j, -inf else; row max
//   pass2: p_j = exp(e_j - max); row sum
//   pass3: out[d] = inv * sum_j p_j * Wh[b,j,h,d], skipping p_j == 0 (sparse)
// ---------------------------------------------------------------------------
__global__ void attn_kernel(const void* __restrict__ mask, float* __restrict__ out) {
    __shared__ float sh_e[N_];
    __shared__ float sred[8];
    __shared__ float sacc[256];
    __shared__ float sscal[2];   // [0]=row max, [1]=inv sum

    int tid = threadIdx.x;
    int bid = blockIdx.x;
    int i = bid % N_;
    int h = (bid / N_) % H_;
    int b = bid / (N_ * H_);

    int kind = g_maskKind;
    float srci = g_src[(b * H_ + h) * N_ + i];
    const float* dstv = g_dst + (size_t)(b * H_ + h) * N_;
    size_t mbase = ((size_t)b * N_ + i) * N_;

    // pass 1: e and max
    float lmax = -INFINITY;
    #pragma unroll
    for (int r = 0; r < 4; ++r) {
        int j = tid + r * 256;
        bool valid;
        if (kind == 0)      valid = ((const unsigned char*)mask)[mbase + j] != 0;
        else if (kind == 1) valid = ((const int*)mask)[mbase + j] != 0;
        else                valid = ((const float*)mask)[mbase + j] != 0.0f;
        float e;
        if (valid) {
            float x = srci + dstv[j];
            e = x > 0.f ? x : 0.2f * x;
        } else {
            e = -INFINITY;
        }
        sh_e[j] = e;
        lmax = fmaxf(lmax, e);
    }
    #pragma unroll
    for (int off = 16; off; off >>= 1)
        lmax = fmaxf(lmax, __shfl_xor_sync(0xFFFFFFFFu, lmax, off));
    if ((tid & 31) == 0) sred[tid >> 5] = lmax;
    __syncthreads();
    if (tid == 0) {
        float m = sred[0];
        #pragma unroll
        for (int k = 1; k < 8; ++k) m = fmaxf(m, sred[k]);
        sscal[0] = m;
    }
    __syncthreads();
    float smax = sscal[0];

    // pass 2: p and sum
    float lsum = 0.f;
    bool finiteMax = (smax > -INFINITY);
    #pragma unroll
    for (int r = 0; r < 4; ++r) {
        int j = tid + r * 256;
        float e = sh_e[j];
        float p = (finiteMax && e > -INFINITY) ? __expf(e - smax) : 0.f;
        sh_e[j] = p;
        lsum += p;
    }
    #pragma unroll
    for (int off = 16; off; off >>= 1)
        lsum += __shfl_xor_sync(0xFFFFFFFFu, lsum, off);
    if ((tid & 31) == 0) sred[tid >> 5] = lsum;
    __syncthreads();
    if (tid == 0) {
        float s = 0.f;
        #pragma unroll
        for (int k = 0; k < 8; ++k) s += sred[k];
        sscal[1] = (s > 0.f) ? (1.0f / s) : 0.f;
    }
    __syncthreads();
    float inv = sscal[1];

    // pass 3: sparse accumulation. 4 groups of 64 threads; group g covers
    // j = g, g+4, ...; thread within group owns head-dim d.
    int d = tid & 63;
    int grp = tid >> 6;
    const float* whbase = g_Wh + (size_t)b * N_ * O_ + h * D_ + d;
    float acc = 0.f;
    for (int j = grp; j < N_; j += 4) {
        float p = sh_e[j];
        if (p != 0.f)
            acc = fmaf(p, whbase[(size_t)j * O_], acc);
    }
    sacc[tid] = acc;
    __syncthreads();
    if (tid < 64) {
        float s = sacc[tid] + sacc[64 + tid] + sacc[128 + tid] + sacc[192 + tid];
        out[(size_t)(b * N_ + i) * O_ + h * D_ + tid] = s * inv;
    }
}

// ---------------------------------------------------------------------------
extern "C" void kernel_launch(void* const* d_in, const int* in_sizes, int n_in,
                              void* d_out, int out_size) {
    const float* h = nullptr;
    const float* W = nullptr;
    const float* a = nullptr;
    const void*  mask = nullptr;

    for (int idx = 0; idx < n_in; ++idx) {
        switch (in_sizes[idx]) {
            case B_ * N_ * K_: h    = (const float*)d_in[idx]; break; // 2097152
            case K_ * O_:      W    = (const float*)d_in[idx]; break; // 65536
            case H_ * 2 * D_:  a    = (const float*)d_in[idx]; break; // 512
            case B_ * N_ * N_: mask = d_in[idx];               break; // 8388608
        }
    }
    // fallback to positional order if sizes were ambiguous
    if (!h)    h    = (const float*)d_in[0];
    if (!W)    W    = (const float*)d_in[1];
    if (!a)    a    = (const float*)d_in[2];
    if (!mask) mask = d_in[3];

    detect_mask_kind<<<1, 256>>>((const unsigned int*)mask);
    gemm_kernel<<<dim3((B_ * N_) / 64, O_ / 64), 256>>>(h, W);
    srcdst_kernel<<<(B_ * H_ * N_) / 8, 256>>>(a);
    attn_kernel<<<B_ * H_ * N_, 256>>>(mask, (float*)d_out);
}

// round 2
// speedup vs baseline: 3.2629x; 3.2629x over previous
#include <cuda_runtime.h>
#include <math.h>
#include <stdint.h>

// GAT layer: B=8, N=1024, IN=256, OUT=256 (H=4 heads x D=64)

#define B_ 8
#define N_ 1024
#define K_ 256
#define O_ 256
#define H_ 4
#define D_ 64

__device__ float g_Wh[B_ * N_ * O_];      // [b*N+n][o]  (o = h*64+d), 32 MB
__device__ float g_src[B_ * H_ * N_];
__device__ float g_dst[B_ * H_ * N_];
__device__ int   g_maskKind;              // 0=uint8, 1=int32, 2=float32

// ---------------------------------------------------------------------------
// Kernel A: classify the bool-mask encoding (see round-0 notes).
// ---------------------------------------------------------------------------
__global__ void detect_mask_kind(const unsigned int* __restrict__ w) {
    __shared__ int sFloat, sBig;
    if (threadIdx.x == 0) { sFloat = 0; sBig = 0; }
    __syncthreads();
    for (int i = threadIdx.x; i < 65536; i += blockDim.x) {
        unsigned int v = w[i];
        if (v == 0x3F800000u) atomicOr(&sFloat, 1);
        else if (v > 1u) atomicOr(&sBig, 1);
    }
    __syncthreads();
    if (threadIdx.x == 0)
        g_maskKind = sFloat ? 2 : (sBig ? 0 : 1);
}

// ---------------------------------------------------------------------------
// Kernel B: Wh = h @ W^T.  M=8192, K=256, O=256. 64x64 tile, 256 threads,
// 4x4 micro-tile per thread, K-tiles of 16.
// ---------------------------------------------------------------------------
__global__ void gemm_kernel(const float* __restrict__ A, const float* __restrict__ Wt) {
    __shared__ float As[16][64];
    __shared__ float Bs[16][64];

    int tid = threadIdx.x;
    int tx = tid & 15;
    int ty = tid >> 4;
    int m0 = blockIdx.x * 64;
    int o0 = blockIdx.y * 64;

    int lr = tid >> 2;
    int lk = (tid & 3) * 4;

    float acc[4][4] = {};

    for (int k0 = 0; k0 < K_; k0 += 16) {
        float4 av = *reinterpret_cast<const float4*>(A  + (size_t)(m0 + lr) * K_ + k0 + lk);
        float4 bv = *reinterpret_cast<const float4*>(Wt + (size_t)(o0 + lr) * K_ + k0 + lk);
        As[lk + 0][lr] = av.x; As[lk + 1][lr] = av.y;
        As[lk + 2][lr] = av.z; As[lk + 3][lr] = av.w;
        Bs[lk + 0][lr] = bv.x; Bs[lk + 1][lr] = bv.y;
        Bs[lk + 2][lr] = bv.z; Bs[lk + 3][lr] = bv.w;
        __syncthreads();

        #pragma unroll
        for (int k = 0; k < 16; ++k) {
            float a[4], b[4];
            #pragma unroll
            for (int i = 0; i < 4; ++i) a[i] = As[k][ty * 4 + i];
            #pragma unroll
            for (int j = 0; j < 4; ++j) b[j] = Bs[k][tx * 4 + j];
            #pragma unroll
            for (int i = 0; i < 4; ++i)
                #pragma unroll
                for (int j = 0; j < 4; ++j)
                    acc[i][j] = fmaf(a[i], b[j], acc[i][j]);
        }
        __syncthreads();
    }

    #pragma unroll
    for (int i = 0; i < 4; ++i)
        #pragma unroll
        for (int j = 0; j < 4; ++j)
            g_Wh[(size_t)(m0 + ty * 4 + i) * O_ + o0 + tx * 4 + j] = acc[i][j];
}

// ---------------------------------------------------------------------------
// Kernel C: src/dst projections. Warp per (b,h,n) row.
// ---------------------------------------------------------------------------
__global__ void srcdst_kernel(const float* __restrict__ a) {
    int warp = (blockIdx.x * blockDim.x + threadIdx.x) >> 5;
    int lane = threadIdx.x & 31;
    if (warp >= B_ * H_ * N_) return;
    int n = warp % N_;
    int h = (warp / N_) % H_;
    int b = warp / (N_ * H_);

    const float* wh = g_Wh + (size_t)(b * N_ + n) * O_ + h * D_;
    const float* ah = a + h * (2 * D_);
    float s = 0.f, t = 0.f;
    #pragma unroll
    for (int d = lane; d < D_; d += 32) {
        float w = wh[d];
        s = fmaf(w, __ldg(ah + d), s);
        t = fmaf(w, __ldg(ah + D_ + d), t);
    }
    #pragma unroll
    for (int off = 16; off; off >>= 1) {
        s += __shfl_down_sync(0xFFFFFFFFu, s, off);
        t += __shfl_down_sync(0xFFFFFFFFu, t, off);
    }
    if (lane == 0) { g_src[warp] = s; g_dst[warp] = t; }
}

// ---------------------------------------------------------------------------
// Kernel D: one block per (b,i), 256 threads, all 4 heads computed by
// 64-thread groups (group = head, lane-in-group = head dim d).
//   phase 0: ballot-compact valid j's into sh_idx (shared across heads)
//   phase 1: per-head e over compacted list; group max
//   phase 2: per-head exp/sum
//   phase 3: out[h*64+d] = inv * sum_k p_k * Wh[b, idx_k, h*64+d]
// ---------------------------------------------------------------------------
__global__ void attn_kernel(const void* __restrict__ mask, float* __restrict__ out) {
    __shared__ unsigned short sh_idx[N_];          // compacted neighbor list
    __shared__ float sh_p[H_][N_];                 // per-head e then p (16KB)
    __shared__ int   sCnt;
    __shared__ float sgmax[H_][2];
    __shared__ float sgsum[H_][2];

    int tid = threadIdx.x;
    int bid = blockIdx.x;                          // b*N + i
    int i = bid & (N_ - 1);
    int b = bid >> 10;
    int lane = tid & 31;
    int warp = tid >> 5;                           // 0..7

    if (tid == 0) sCnt = 0;
    __syncthreads();

    int kind = g_maskKind;
    size_t mbase = ((size_t)b * N_ + i) * N_;

    // phase 0: compaction. 8 warps x 4 rounds x 32 contiguous j's.
    #pragma unroll
    for (int r = 0; r < 4; ++r) {
        int j = r * 256 + warp * 32 + lane;
        bool valid;
        if (kind == 0)      valid = ((const unsigned char*)mask)[mbase + j] != 0;
        else if (kind == 1) valid = ((const int*)mask)[mbase + j] != 0;
        else                valid = ((const float*)mask)[mbase + j] != 0.0f;
        unsigned bal = __ballot_sync(0xFFFFFFFFu, valid);
        int base = 0;
        if (lane == 0) base = atomicAdd(&sCnt, __popc(bal));
        base = __shfl_sync(0xFFFFFFFFu, base, 0);
        if (valid) {
            int pos = base + __popc(bal & ((1u << lane) - 1u));
            sh_idx[pos] = (unsigned short)j;
        }
    }
    __syncthreads();
    int cnt = sCnt;

    int h   = tid >> 6;                            // head for this group
    int l64 = tid & 63;                            // lane within group (= d)
    int wig = (tid >> 5) & 1;                      // warp-in-group

    const float* dstv = g_dst + (size_t)(b * H_ + h) * N_;
    float srci = g_src[(b * H_ + h) * N_ + i];

    // phase 1: e over compacted list + group max
    float lmax = -INFINITY;
    for (int k = l64; k < cnt; k += 64) {
        float x = srci + dstv[sh_idx[k]];
        float e = x > 0.f ? x : 0.2f * x;
        sh_p[h][k] = e;
        lmax = fmaxf(lmax, e);
    }
    #pragma unroll
    for (int off = 16; off; off >>= 1)
        lmax = fmaxf(lmax, __shfl_xor_sync(0xFFFFFFFFu, lmax, off));
    if (lane == 0) sgmax[h][wig] = lmax;
    __syncthreads();
    float m = fmaxf(sgmax[h][0], sgmax[h][1]);

    // phase 2: exp + group sum
    float lsum = 0.f;
    for (int k = l64; k < cnt; k += 64) {
        float p = __expf(sh_p[h][k] - m);
        sh_p[h][k] = p;
        lsum += p;
    }
    #pragma unroll
    for (int off = 16; off; off >>= 1)
        lsum += __shfl_xor_sync(0xFFFFFFFFu, lsum, off);
    if (lane == 0) sgsum[h][wig] = lsum;
    __syncthreads();
    float ssum = sgsum[h][0] + sgsum[h][1];
    float inv = (ssum > 0.f) ? (1.0f / ssum) : 0.f;

    // phase 3: gather-accumulate over compacted list. All 64 lanes of the
    // group walk the same k (p and idx broadcast from shared), lane owns d.
    const float* whb = g_Wh + (size_t)b * N_ * O_ + h * D_ + l64;
    float acc = 0.f;
    int k = 0;
    for (; k + 4 <= cnt; k += 4) {
        int j0 = sh_idx[k + 0], j1 = sh_idx[k + 1];
        int j2 = sh_idx[k + 2], j3 = sh_idx[k + 3];
        float p0 = sh_p[h][k + 0], p1 = sh_p[h][k + 1];
        float p2 = sh_p[h][k + 2], p3 = sh_p[h][k + 3];
        float w0 = whb[(size_t)j0 * O_];
        float w1 = whb[(size_t)j1 * O_];
        float w2 = whb[(size_t)j2 * O_];
        float w3 = whb[(size_t)j3 * O_];
        acc = fmaf(p0, w0, acc);
        acc = fmaf(p1, w1, acc);
        acc = fmaf(p2, w2, acc);
        acc = fmaf(p3, w3, acc);
    }
    for (; k < cnt; ++k)
        acc = fmaf(sh_p[h][k], whb[(size_t)sh_idx[k] * O_], acc);

    out[(size_t)bid * O_ + h * D_ + l64] = acc * inv;
}

// ---------------------------------------------------------------------------
extern "C" void kernel_launch(void* const* d_in, const int* in_sizes, int n_in,
                              void* d_out, int out_size) {
    const float* h = nullptr;
    const float* W = nullptr;
    const float* a = nullptr;
    const void*  mask = nullptr;

    for (int idx = 0; idx < n_in; ++idx) {
        switch (in_sizes[idx]) {
            case B_ * N_ * K_: h    = (const float*)d_in[idx]; break;
            case K_ * O_:      W    = (const float*)d_in[idx]; break;
            case H_ * 2 * D_:  a    = (const float*)d_in[idx]; break;
            case B_ * N_ * N_: mask = d_in[idx];               break;
        }
    }
    if (!h)    h    = (const float*)d_in[0];
    if (!W)    W    = (const float*)d_in[1];
    if (!a)    a    = (const float*)d_in[2];
    if (!mask) mask = d_in[3];

    detect_mask_kind<<<1, 256>>>((const unsigned int*)mask);
    gemm_kernel<<<dim3((B_ * N_) / 64, O_ / 64), 256>>>(h, W);
    srcdst_kernel<<<(B_ * H_ * N_) / 8, 256>>>(a);
    attn_kernel<<<B_ * N_, 256>>>(mask, (float*)d_out);
}

// round 3
// speedup vs baseline: 5.1539x; 1.5796x over previous
#include <cuda_runtime.h>
#include <math.h>
#include <stdint.h>

// GAT layer: B=8, N=1024, IN=256, OUT=256 (H=4 heads x D=64)

#define B_ 8
#define N_ 1024
#define K_ 256
#define O_ 256
#define H_ 4
#define D_ 64

__device__ float g_Wh[B_ * N_ * O_];      // [b*N+n][o]  (o = h*64+d), 32 MB
__device__ float g_src[B_ * H_ * N_];
__device__ float g_dst[B_ * H_ * N_];
__device__ int   g_maskKind;              // 0=uint8, 1=int32, 2=float32

// ---------------------------------------------------------------------------
// Kernel A: classify the bool-mask encoding. 8192 words is statistically
// certain evidence for all three encodings (mask density ~10%).
// ---------------------------------------------------------------------------
__global__ void detect_mask_kind(const unsigned int* __restrict__ w) {
    __shared__ int sFloat, sBig;
    if (threadIdx.x == 0) { sFloat = 0; sBig = 0; }
    __syncthreads();
    #pragma unroll 4
    for (int i = threadIdx.x; i < 8192; i += blockDim.x) {
        unsigned int v = w[i];
        if (v == 0x3F800000u) atomicOr(&sFloat, 1);
        else if (v > 1u) atomicOr(&sBig, 1);
    }
    __syncthreads();
    if (threadIdx.x == 0)
        g_maskKind = sFloat ? 2 : (sBig ? 0 : 1);
}

// ---------------------------------------------------------------------------
// Kernel B: Wh = h @ W^T with fused src/dst epilogue.
// 128x64 tile (o-block = one head), 256 threads, 8x4 micro-tile.
// Per-thread columns are strided: d = tx + 16c (conflict-free B reads).
// Epilogue: shfl-reduce acc . a_src / a_dst across tx -> g_src/g_dst.
// ---------------------------------------------------------------------------
__global__ void __launch_bounds__(256) gemm_kernel(
    const float* __restrict__ A, const float* __restrict__ Wt,
    const float* __restrict__ avec)
{
    __shared__ float As[16][128];   // [k][m]
    __shared__ float Bs[16][64];    // [k][o]

    int tid = threadIdx.x;
    int tx = tid & 15;
    int ty = tid >> 4;
    int m0 = blockIdx.x * 128;
    int h  = blockIdx.y;
    int o0 = h * 64;

    // loader mapping
    int arow = tid >> 1;            // 0..127
    int aoff = (tid & 1) * 8;       // 0 or 8 (8 contiguous k-floats)
    int brow = tid & 63;            // 0..63
    int boff = (tid >> 6) * 4;      // 0,4,8,12

    float acc[8][4] = {};

    for (int k0 = 0; k0 < K_; k0 += 16) {
        float4 a0 = *reinterpret_cast<const float4*>(A + (size_t)(m0 + arow) * K_ + k0 + aoff);
        float4 a1 = *reinterpret_cast<const float4*>(A + (size_t)(m0 + arow) * K_ + k0 + aoff + 4);
        float4 bv = *reinterpret_cast<const float4*>(Wt + (size_t)(o0 + brow) * K_ + k0 + boff);
        __syncthreads();
        As[aoff + 0][arow] = a0.x; As[aoff + 1][arow] = a0.y;
        As[aoff + 2][arow] = a0.z; As[aoff + 3][arow] = a0.w;
        As[aoff + 4][arow] = a1.x; As[aoff + 5][arow] = a1.y;
        As[aoff + 6][arow] = a1.z; As[aoff + 7][arow] = a1.w;
        Bs[boff + 0][brow] = bv.x; Bs[boff + 1][brow] = bv.y;
        Bs[boff + 2][brow] = bv.z; Bs[boff + 3][brow] = bv.w;
        __syncthreads();

        #pragma unroll
        for (int k = 0; k < 16; ++k) {
            float4 t0 = *reinterpret_cast<const float4*>(&As[k][ty * 8]);
            float4 t1 = *reinterpret_cast<const float4*>(&As[k][ty * 8 + 4]);
            float av[8] = {t0.x, t0.y, t0.z, t0.w, t1.x, t1.y, t1.z, t1.w};
            float bv4[4];
            #pragma unroll
            for (int c = 0; c < 4; ++c) bv4[c] = Bs[k][tx + 16 * c];
            #pragma unroll
            for (int i = 0; i < 8; ++i)
                #pragma unroll
                for (int c = 0; c < 4; ++c)
                    acc[i][c] = fmaf(av[i], bv4[c], acc[i][c]);
        }
    }

    // write Wh
    #pragma unroll
    for (int i = 0; i < 8; ++i) {
        float* dst = g_Wh + (size_t)(m0 + ty * 8 + i) * O_ + o0 + tx;
        #pragma unroll
        for (int c = 0; c < 4; ++c) dst[16 * c] = acc[i][c];
    }

    // fused src/dst epilogue
    float asv[4], adv[4];
    #pragma unroll
    for (int c = 0; c < 4; ++c) {
        asv[c] = __ldg(avec + h * (2 * D_) + tx + 16 * c);
        adv[c] = __ldg(avec + h * (2 * D_) + D_ + tx + 16 * c);
    }
    int b = m0 >> 10;
    int nbase = (m0 & (N_ - 1)) + ty * 8;
    #pragma unroll
    for (int i = 0; i < 8; ++i) {
        float s = 0.f, t = 0.f;
        #pragma unroll
        for (int c = 0; c < 4; ++c) {
            s = fmaf(acc[i][c], asv[c], s);
            t = fmaf(acc[i][c], adv[c], t);
        }
        #pragma unroll
        for (int off = 8; off; off >>= 1) {
            s += __shfl_xor_sync(0xFFFFFFFFu, s, off);
            t += __shfl_xor_sync(0xFFFFFFFFu, t, off);
        }
        if (tx == 0) {
            g_src[(b * H_ + h) * N_ + nbase + i] = s;
            g_dst[(b * H_ + h) * N_ + nbase + i] = t;
        }
    }
}

// ---------------------------------------------------------------------------
// Kernel C: attention. One block per (b,i), 256 threads.
//   phase 0: ballot-compact valid j's into sh_idx
//   phase 1: e_k (+ packed j bits) per head, group max     (64-lane groups)
//   phase 2: p_k = exp(e-m), sum, inv
//   phase 3: warp-per-(head,half): float2 gather-accumulate over compacted
//            list, packed (p,j) loaded with one LDS.64 broadcast
// ---------------------------------------------------------------------------
__global__ void __launch_bounds__(256) attn_kernel(
    const void* __restrict__ mask, float* __restrict__ out)
{
    __shared__ unsigned short sh_idx[N_];      // 2KB
    __shared__ float2 sh_pj[H_][N_];           // 32KB: (e|p, j-bits)
    __shared__ int   sCnt;
    __shared__ float sgred[H_][2];
    __shared__ float sinv[H_];
    __shared__ float sacc[8][64];              // 2KB

    int tid = threadIdx.x;
    int bid = blockIdx.x;                      // b*N + i
    int i = bid & (N_ - 1);
    int b = bid >> 10;
    int lane = tid & 31;
    int warp = tid >> 5;

    if (tid == 0) sCnt = 0;
    __syncthreads();

    int kind = g_maskKind;
    size_t mbase = ((size_t)b * N_ + i) * N_;

    // phase 0: compaction
    #pragma unroll
    for (int r = 0; r < 4; ++r) {
        int j = r * 256 + warp * 32 + lane;
        bool valid;
        if (kind == 0)      valid = ((const unsigned char*)mask)[mbase + j] != 0;
        else if (kind == 1) valid = ((const int*)mask)[mbase + j] != 0;
        else                valid = ((const float*)mask)[mbase + j] != 0.0f;
        unsigned bal = __ballot_sync(0xFFFFFFFFu, valid);
        int base = 0;
        if (lane == 0) base = atomicAdd(&sCnt, __popc(bal));
        base = __shfl_sync(0xFFFFFFFFu, base, 0);
        if (valid)
            sh_idx[base + __popc(bal & ((1u << lane) - 1u))] = (unsigned short)j;
    }
    __syncthreads();
    int cnt = sCnt;

    int h   = tid >> 6;
    int l64 = tid & 63;
    int wig = (tid >> 5) & 1;

    const float* dstv = g_dst + (size_t)(b * H_ + h) * N_;
    float srci = g_src[(b * H_ + h) * N_ + i];

    // phase 1: e + packed idx, group max
    float lmax = -INFINITY;
    for (int k = l64; k < cnt; k += 64) {
        unsigned j = sh_idx[k];
        float x = srci + dstv[j];
        float e = x > 0.f ? x : 0.2f * x;
        sh_pj[h][k] = make_float2(e, __uint_as_float(j));
        lmax = fmaxf(lmax, e);
    }
    #pragma unroll
    for (int off = 16; off; off >>= 1)
        lmax = fmaxf(lmax, __shfl_xor_sync(0xFFFFFFFFu, lmax, off));
    if (lane == 0) sgred[h][wig] = lmax;
    __syncthreads();
    float m = fmaxf(sgred[h][0], sgred[h][1]);

    // phase 2: exp + sum
    float lsum = 0.f;
    for (int k = l64; k < cnt; k += 64) {
        float p = __expf(sh_pj[h][k].x - m);
        sh_pj[h][k].x = p;
        lsum += p;
    }
    #pragma unroll
    for (int off = 16; off; off >>= 1)
        lsum += __shfl_xor_sync(0xFFFFFFFFu, lsum, off);
    if (lane == 0) sgred[h][wig] = lsum;
    __syncthreads();
    if (l64 == 0) {
        float ssum = sgred[h][0] + sgred[h][1];
        sinv[h] = (ssum > 0.f) ? (1.0f / ssum) : 0.f;
    }

    // phase 3: gather-accumulate. warp = (head, half); lane owns d-pair.
    {
        int hh  = warp >> 1;
        int half = warp & 1;
        const float2* whb = reinterpret_cast<const float2*>(
            g_Wh + (size_t)b * N_ * O_ + hh * D_) + lane;
        float2 acc = make_float2(0.f, 0.f);
        int k = half;
        while (k + 2 < cnt) {
            float2 pj0 = sh_pj[hh][k];
            float2 pj1 = sh_pj[hh][k + 2];
            unsigned j0 = __float_as_uint(pj0.y);
            unsigned j1 = __float_as_uint(pj1.y);
            float2 w0 = whb[(size_t)j0 * 128];
            float2 w1 = whb[(size_t)j1 * 128];
            acc.x = fmaf(pj0.x, w0.x, acc.x);
            acc.y = fmaf(pj0.x, w0.y, acc.y);
            acc.x = fmaf(pj1.x, w1.x, acc.x);
            acc.y = fmaf(pj1.x, w1.y, acc.y);
            k += 4;
        }
        if (k < cnt) {
            float2 pj = sh_pj[hh][k];
            unsigned j = __float_as_uint(pj.y);
            float2 w0 = whb[(size_t)j * 128];
            acc.x = fmaf(pj.x, w0.x, acc.x);
            acc.y = fmaf(pj.x, w0.y, acc.y);
        }
        sacc[warp][lane * 2]     = acc.x;
        sacc[warp][lane * 2 + 1] = acc.y;
    }
    __syncthreads();

    // combine halves + scale + store
    {
        int hh = tid >> 6;
        int d  = tid & 63;
        float v = (sacc[2 * hh][d] + sacc[2 * hh + 1][d]) * sinv[hh];
        out[(size_t)bid * O_ + hh * D_ + d] = v;
    }
}

// ---------------------------------------------------------------------------
extern "C" void kernel_launch(void* const* d_in, const int* in_sizes, int n_in,
                              void* d_out, int out_size) {
    const float* h = nullptr;
    const float* W = nullptr;
    const float* a = nullptr;
    const void*  mask = nullptr;

    for (int idx = 0; idx < n_in; ++idx) {
        switch (in_sizes[idx]) {
            case B_ * N_ * K_: h    = (const float*)d_in[idx]; break;
            case K_ * O_:      W    = (const float*)d_in[idx]; break;
            case H_ * 2 * D_:  a    = (const float*)d_in[idx]; break;
            case B_ * N_ * N_: mask = d_in[idx];               break;
        }
    }
    if (!h)    h    = (const float*)d_in[0];
    if (!W)    W    = (const float*)d_in[1];
    if (!a)    a    = (const float*)d_in[2];
    if (!mask) mask = d_in[3];

    detect_mask_kind<<<1, 256>>>((const unsigned int*)mask);
    gemm_kernel<<<dim3((B_ * N_) / 128, H_), 256>>>(h, W, a);
    attn_kernel<<<B_ * N_, 256>>>(mask, (float*)d_out);
}